// round 7
// baseline (speedup 1.0000x reference)
#include <cuda_runtime.h>
#include <cuda_fp16.h>
#include <cstdint>

// GRU fused kernel v4: B=16, T=60, S=2000, C=64, H=64.
// One WARP owns 16 sequences and ALL 192 gate columns -> warp-private
// recurrence, h in f32 registers, no barriers in the time loop.
// v4: (a) depth-2 rotating ldsm prefetch (3 buffers) to cover the ~29cyc
// smem latency that left issue at 41%; (b) 64-thread CTAs (2 warps), 4
// CTAs/SM with per-CTA weight copies, to fix the 250-CTA wave-tail
// imbalance (2.0 -> 1.75 CTA-times) and de-correlate warp phases.

namespace {

constexpr int kT = 60, kS = 2000, kC = 64, kH = 64, kG = 192;
constexpr int PITCH = 72;      // fp16 elems per weight row (144B) -> conflict-free ldsm
constexpr int THREADS = 64;    // 2 warps, 32 rows per CTA
constexpr int NROWS = 16 * 2000;

constexpr int OFF_WIH = 0;
constexpr int OFF_WHH = OFF_WIH + kG * PITCH * 2;
constexpr int OFF_BRZ = OFF_WHH + kG * PITCH * 2;   // f32[128]
constexpr int OFF_BIN = OFF_BRZ + 128 * 4;          // f32[64]
constexpr int OFF_BHN = OFF_BIN + 64 * 4;           // f32[64]
constexpr int SMEM_BYTES = OFF_BHN + 64 * 4;        // 56320 B -> 4 CTAs/SM

__device__ __forceinline__ uint32_t smem_u32(const void* p) {
  return (uint32_t)__cvta_generic_to_shared(p);
}

__device__ __forceinline__ void ldsm4(uint32_t r[4], uint32_t addr) {
  asm volatile("ldmatrix.sync.aligned.m8n8.x4.shared.b16 {%0,%1,%2,%3}, [%4];\n"
               : "=r"(r[0]), "=r"(r[1]), "=r"(r[2]), "=r"(r[3]) : "r"(addr));
}

__device__ __forceinline__ void mma16816(float d[4], const uint32_t a[4],
                                         const uint32_t b0, const uint32_t b1) {
  asm volatile(
      "mma.sync.aligned.m16n8k16.row.col.f32.f16.f16.f32 "
      "{%0,%1,%2,%3},{%4,%5,%6,%7},{%8,%9},{%0,%1,%2,%3};\n"
      : "+f"(d[0]), "+f"(d[1]), "+f"(d[2]), "+f"(d[3])
      : "r"(a[0]), "r"(a[1]), "r"(a[2]), "r"(a[3]), "r"(b0), "r"(b1));
}

__device__ __forceinline__ uint32_t pack_f16x2(float a, float b) {
  __half2 h = __floats2half2_rn(a, b);
  return *reinterpret_cast<uint32_t*>(&h);
}

__device__ __forceinline__ float fsigmoid(float x) {
  return __fdividef(1.0f, 1.0f + __expf(-x));
}
__device__ __forceinline__ float ftanh_acc(float x) {
  return __fdividef(2.0f, 1.0f + __expf(-2.0f * x)) - 1.0f;
}

}  // namespace

__global__ void __launch_bounds__(THREADS, 4)
gru_fused_kernel(const float* __restrict__ chars,
                 const float* __restrict__ Wih,
                 const float* __restrict__ Whh,
                 const float* __restrict__ bih,
                 const float* __restrict__ bhh,
                 float* __restrict__ out) {
  extern __shared__ char smem[];
  __half* wih_s = reinterpret_cast<__half*>(smem + OFF_WIH);
  __half* whh_s = reinterpret_cast<__half*>(smem + OFF_WHH);
  float* brz = reinterpret_cast<float*>(smem + OFF_BRZ);
  float* bin_s = reinterpret_cast<float*>(smem + OFF_BIN);
  float* bhn_s = reinterpret_cast<float*>(smem + OFF_BHN);

  const int tid = threadIdx.x;
  const int lane = tid & 31;
  const int wid = tid >> 5;

  // ---- one-time init: fp16 weights (padded pitch), biases ----
  for (int i = tid; i < kG * kC; i += THREADS) {
    const int g = i >> 6, c = i & 63;
    wih_s[g * PITCH + c] = __float2half_rn(Wih[i]);
    whh_s[g * PITCH + c] = __float2half_rn(Whh[i]);
  }
  for (int i = tid; i < 128; i += THREADS) brz[i] = bih[i] + bhh[i];
  if (tid < 64) {
    bin_s[tid] = bih[128 + tid];
    bhn_s[tid] = bhh[128 + tid];
  }
  __syncthreads();  // the only block-wide barrier

  // ---- per-warp geometry ----
  const int warp_row0 = (blockIdx.x * 2 + wid) * 16;  // 16 rows per warp
  const int bb = warp_row0 / kS;
  const int ss = warp_row0 - bb * kS;
  const int lr = lane >> 2;          // 0..7
  const int c0 = (lane & 3) * 2;     // 0,2,4,6

  const float* pxa = chars + ((size_t)bb * kT * kS + (ss + lr)) * (size_t)kC;
  const float* pxb = pxa + 8 * kC;
  const size_t tstride = (size_t)kS * kC;

  // ldsm4 lane offset for B fragments
  const int sel = lane >> 3;
  const int b_lane_off = ((lane & 7) + 8 * (sel >> 1)) * (PITCH * 2) + (sel & 1) * 16;
  const uint32_t wih_b = smem_u32(wih_s) + b_lane_off;
  const uint32_t whh_b = smem_u32(whh_s) + b_lane_off;

  // h state in f32 C-fragment layout; tile j covers cols 8j..8j+7
  float hf[8][4];
#pragma unroll
  for (int j = 0; j < 8; ++j)
#pragma unroll
    for (int e = 0; e < 4; ++e) hf[j][e] = 0.0f;

  for (int t = 0; t < kT; ++t) {
    // ---- load x_t and pack to fp16 A-fragments (latency hidden by h-GEMM) ----
    uint32_t xa[4][4];  // [kk][frag]
#pragma unroll
    for (int kk = 0; kk < 4; ++kk) {
      const float2 v0 = *reinterpret_cast<const float2*>(pxa + 16 * kk + c0);
      const float2 v1 = *reinterpret_cast<const float2*>(pxb + 16 * kk + c0);
      const float2 v2 = *reinterpret_cast<const float2*>(pxa + 16 * kk + 8 + c0);
      const float2 v3 = *reinterpret_cast<const float2*>(pxb + 16 * kk + 8 + c0);
      xa[kk][0] = pack_f16x2(v0.x, v0.y);
      xa[kk][1] = pack_f16x2(v1.x, v1.y);
      xa[kk][2] = pack_f16x2(v2.x, v2.y);
      xa[kk][3] = pack_f16x2(v3.x, v3.y);
    }
    pxa += tstride;
    pxb += tstride;

    // pack h A-fragments (C-frag layout matches A-frag layout)
    uint32_t ha[4][4];
#pragma unroll
    for (int kk = 0; kk < 4; ++kk) {
      ha[kk][0] = pack_f16x2(hf[2 * kk][0], hf[2 * kk][1]);
      ha[kk][1] = pack_f16x2(hf[2 * kk][2], hf[2 * kk][3]);
      ha[kk][2] = pack_f16x2(hf[2 * kk + 1][0], hf[2 * kk + 1][1]);
      ha[kk][3] = pack_f16x2(hf[2 * kk + 1][2], hf[2 * kk + 1][3]);
    }

    // accumulators: tiles 0-7 r, 8-15 z, 16-23 n(x-path); accHN = h-n-path
    float acc[24][4];
    float accHN[8][4];
#pragma unroll
    for (int j = 0; j < 24; ++j)
#pragma unroll
      for (int e = 0; e < 4; ++e) acc[j][e] = 0.0f;
#pragma unroll
    for (int j = 0; j < 8; ++j)
#pragma unroll
      for (int e = 0; e < 4; ++e) accHN[j][e] = 0.0f;

    // ---- h-path GEMM: gh = h @ Whh^T, depth-2 rotating prefetch ----
    {
      auto pref = [&](int u, uint32_t* b) {
        if (u < 48) ldsm4(b, whh_b + (u / 12) * 32 + (u % 12) * (16 * PITCH * 2));
      };
      auto unit = [&](int u, const uint32_t* b) {
        const int kk = u / 12, jp = u % 12;
        float* d0 = (jp < 8) ? acc[2 * jp] : accHN[2 * (jp - 8)];
        float* d1 = (jp < 8) ? acc[2 * jp + 1] : accHN[2 * (jp - 8) + 1];
        mma16816(d0, ha[kk], b[0], b[1]);
        mma16816(d1, ha[kk], b[2], b[3]);
      };
      uint32_t B0[4], B1[4], B2[4];
      pref(0, B0);
      pref(1, B1);
#pragma unroll
      for (int g = 0; g < 16; ++g) {
        pref(3 * g + 2, B2); unit(3 * g + 0, B0);
        pref(3 * g + 3, B0); unit(3 * g + 1, B1);
        pref(3 * g + 4, B1); unit(3 * g + 2, B2);
      }
    }

    // ---- x-path GEMM: gi = x @ Wih^T, depth-2 rotating prefetch ----
    {
      auto pref = [&](int u, uint32_t* b) {
        if (u < 48) ldsm4(b, wih_b + (u / 12) * 32 + (u % 12) * (16 * PITCH * 2));
      };
      auto unit = [&](int u, const uint32_t* b) {
        const int kk = u / 12, jp = u % 12;
        mma16816(acc[2 * jp], xa[kk], b[0], b[1]);
        mma16816(acc[2 * jp + 1], xa[kk], b[2], b[3]);
      };
      uint32_t B0[4], B1[4], B2[4];
      pref(0, B0);
      pref(1, B1);
#pragma unroll
      for (int g = 0; g < 16; ++g) {
        pref(3 * g + 2, B2); unit(3 * g + 0, B0);
        pref(3 * g + 3, B0); unit(3 * g + 1, B1);
        pref(3 * g + 4, B1); unit(3 * g + 2, B2);
      }
    }

    // ---- elementwise GRU update (warp-private, no sync) ----
#pragma unroll
    for (int j = 0; j < 8; ++j) {
      const float2 bR = *reinterpret_cast<const float2*>(brz + 8 * j + c0);
      const float2 bZ = *reinterpret_cast<const float2*>(brz + 64 + 8 * j + c0);
      const float2 bN = *reinterpret_cast<const float2*>(bin_s + 8 * j + c0);
      const float2 bHN = *reinterpret_cast<const float2*>(bhn_s + 8 * j + c0);
#pragma unroll
      for (int half = 0; half < 2; ++half) {
        const int e0 = half * 2, e1 = half * 2 + 1;
        const float r0 = fsigmoid(acc[j][e0] + bR.x);
        const float r1 = fsigmoid(acc[j][e1] + bR.y);
        const float z0 = fsigmoid(acc[8 + j][e0] + bZ.x);
        const float z1 = fsigmoid(acc[8 + j][e1] + bZ.y);
        const float hn0 = accHN[j][e0] + bHN.x;
        const float hn1 = accHN[j][e1] + bHN.y;
        const float n0 = ftanh_acc(acc[16 + j][e0] + bN.x + r0 * hn0);
        const float n1 = ftanh_acc(acc[16 + j][e1] + bN.y + r1 * hn1);
        hf[j][e0] = n0 + z0 * (hf[j][e0] - n0);
        hf[j][e1] = n1 + z1 * (hf[j][e1] - n1);
      }
    }
  }

  // ---- write final h (f32 state, exact) ----
  {
    float* poa = out + (size_t)(warp_row0 + lr) * kH;
    float* pob = out + (size_t)(warp_row0 + lr + 8) * kH;
#pragma unroll
    for (int j = 0; j < 8; ++j) {
      float2 va, vb;
      va.x = hf[j][0]; va.y = hf[j][1];
      vb.x = hf[j][2]; vb.y = hf[j][3];
      *reinterpret_cast<float2*>(poa + 8 * j + c0) = va;
      *reinterpret_cast<float2*>(pob + 8 * j + c0) = vb;
    }
  }
}

extern "C" void kernel_launch(void* const* d_in, const int* in_sizes, int n_in,
                              void* d_out, int out_size) {
  const float* chars = (const float*)d_in[0];
  const float* Wih = (const float*)d_in[1];
  const float* Whh = (const float*)d_in[2];
  const float* bih = (const float*)d_in[3];
  const float* bhh = (const float*)d_in[4];
  float* out = (float*)d_out;

  cudaFuncSetAttribute(gru_fused_kernel,
                       cudaFuncAttributeMaxDynamicSharedMemorySize, SMEM_BYTES);

  const int grid = NROWS / 32;  // 1000 CTAs, 2 warps each, 16 rows/warp
  gru_fused_kernel<<<grid, THREADS, SMEM_BYTES>>>(chars, Wih, Whh, bih, bhh, out);
}